// round 3
// baseline (speedup 1.0000x reference)
#include <cuda_runtime.h>
#include <cuda_bf16.h>
#include <cstdint>

// Closed-form per-(batch,class) reduction of the symmetric-pair loss.
// For a group of n points of one symmetric class (c in {0,1,2}), with
// u_i = x_i - CENTER_X:
//   sum_{i<j} (u_i+u_j)^2 = (n-2)*Sum(u^2) + (Sum u)^2
//   sum_{i<j} (y_i-y_j)^2 =  n   *Sum(y^2) - (Sum y)^2
//   #pairs                =  n(n-1)/2
// Both identities are exactly 0 for n in {0,1}.
//
// Single launch: one cluster of 8 CTAs (co-scheduled -> deadlock-free
// cross-CTA reduction through DSMEM, no global atomics).

#define CENTER_X 0.5f
#define BATCH 256
#define NPTS  512
#define CLUSTER 8
#define TPB   1024  // 32 warps -> 32 batches per CTA, 1 warp per batch

__device__ __forceinline__ uint32_t smem_u32(const void* p) {
    uint32_t a;
    asm("{ .reg .u64 t; cvta.to.shared.u64 t, %1; cvt.u32.u64 %0, t; }"
        : "=r"(a) : "l"(p));
    return a;
}

__device__ __forceinline__ uint32_t mapa_sh(uint32_t addr, uint32_t rank) {
    uint32_t r;
    asm("mapa.shared::cluster.u32 %0, %1, %2;" : "=r"(r) : "r"(addr), "r"(rank));
    return r;
}

__device__ __forceinline__ double ld_dsmem_f64(uint32_t addr) {
    unsigned long long v;
    asm volatile("ld.shared::cluster.b64 %0, [%1];" : "=l"(v) : "r"(addr));
    return __longlong_as_double((long long)v);
}

__device__ __forceinline__ void cluster_sync_() {
    asm volatile("barrier.cluster.arrive.aligned;" ::: "memory");
    asm volatile("barrier.cluster.wait.aligned;" ::: "memory");
}

__global__ void __launch_bounds__(TPB, 1) __cluster_dims__(CLUSTER, 1, 1)
sym_cluster(const float* __restrict__ kp, const int* __restrict__ cls,
            float* __restrict__ out) {
    __shared__ double s_loss[32], s_cnt[32];
    __shared__ double s_part[2];  // this CTA's (loss, count)

    const int t = threadIdx.x;
    const int w = t >> 5, l = t & 31;
    uint32_t rank;
    asm("mov.u32 %0, %%cluster_ctarank;" : "=r"(rank));

    // Warp w of CTA rank handles batch b entirely.
    const int b = (int)rank * 32 + w;
    const float4* kp4 = reinterpret_cast<const float4*>(kp) + (size_t)b * (NPTS / 2);
    const int4*   c4p = reinterpret_cast<const int4*>(cls) + (size_t)b * (NPTS / 4);

    float su[3], su2[3], sy[3], sy2[3], cn[3];
#pragma unroll
    for (int k = 0; k < 3; k++) { su[k] = su2[k] = sy[k] = sy2[k] = cn[k] = 0.0f; }

#pragma unroll
    for (int s = 0; s < 4; s++) {
        const int g = l + 32 * s;            // point-group of 4
        const int4   c4 = c4p[g];
        const float4 a  = kp4[2 * g];        // points 4g, 4g+1
        const float4 q  = kp4[2 * g + 1];    // points 4g+2, 4g+3

        const float px[4] = {a.x, a.z, q.x, q.z};
        const float py[4] = {a.y, a.w, q.y, q.w};
        const int   pc[4] = {c4.x, c4.y, c4.z, c4.w};
#pragma unroll
        for (int j = 0; j < 4; j++) {
            const float u = px[j] - CENTER_X;
            const float y = py[j];
#pragma unroll
            for (int k = 0; k < 3; k++) {
                if (pc[j] == k) {
                    su[k]  += u;
                    su2[k]  = fmaf(u, u, su2[k]);
                    sy[k]  += y;
                    sy2[k]  = fmaf(y, y, sy2[k]);
                    cn[k]  += 1.0f;
                }
            }
        }
    }

    // Intra-warp reduction of the 15 accumulators.
#pragma unroll
    for (int off = 16; off > 0; off >>= 1) {
#pragma unroll
        for (int k = 0; k < 3; k++) {
            su[k]  += __shfl_down_sync(0xffffffffu, su[k],  off);
            su2[k] += __shfl_down_sync(0xffffffffu, su2[k], off);
            sy[k]  += __shfl_down_sync(0xffffffffu, sy[k],  off);
            sy2[k] += __shfl_down_sync(0xffffffffu, sy2[k], off);
            cn[k]  += __shfl_down_sync(0xffffffffu, cn[k],  off);
        }
    }

    if (l == 0) {
        double loss = 0.0, count = 0.0;
#pragma unroll
        for (int k = 0; k < 3; k++) {
            const double n  = (double)cn[k];
            const double SU = (double)su[k],  SU2 = (double)su2[k];
            const double SY = (double)sy[k],  SY2 = (double)sy2[k];
            loss  += (n - 2.0) * SU2 + SU * SU + n * SY2 - SY * SY;
            count += n * (n - 1.0) * 0.5;
        }
        s_loss[w] = loss;
        s_cnt[w]  = count;
    }
    __syncthreads();

    // Warp 0 reduces the 32 per-warp partials -> CTA partial in s_part.
    if (w == 0) {
        double L = s_loss[l], C = s_cnt[l];
#pragma unroll
        for (int off = 16; off > 0; off >>= 1) {
            L += __shfl_down_sync(0xffffffffu, L, off);
            C += __shfl_down_sync(0xffffffffu, C, off);
        }
        if (l == 0) { s_part[0] = L; s_part[1] = C; }
    }

    // Make s_part visible cluster-wide, then rank 0 gathers via DSMEM.
    cluster_sync_();

    if (rank == 0 && w == 0) {
        double L = 0.0, C = 0.0;
        if (l < CLUSTER) {
            const uint32_t base = mapa_sh(smem_u32(s_part), (uint32_t)l);
            L = ld_dsmem_f64(base);
            C = ld_dsmem_f64(base + 8);
        }
#pragma unroll
        for (int off = 4; off > 0; off >>= 1) {
            L += __shfl_down_sync(0xffffffffu, L, off);
            C += __shfl_down_sync(0xffffffffu, C, off);
        }
        if (l == 0) {
            const double c = C < 1.0 ? 1.0 : C;
            out[0] = (float)(L / c);
        }
    }

    // Keep all CTAs' SMEM alive until rank 0 has finished reading.
    cluster_sync_();
}

extern "C" void kernel_launch(void* const* d_in, const int* in_sizes, int n_in,
                              void* d_out, int out_size) {
    const float* kp  = (const float*)d_in[0];  // [256, 512, 2] f32
    const int*   cls = (const int*)d_in[1];    // [256, 512] i32
    float* out = (float*)d_out;

    sym_cluster<<<CLUSTER, TPB>>>(kp, cls, out);
}

// round 4
// speedup vs baseline: 1.4699x; 1.4699x over previous
#include <cuda_runtime.h>
#include <cuda_bf16.h>
#include <cstdint>

// Closed-form per-(batch,class) reduction of the symmetric-pair loss.
// For a group of n points of one symmetric class (c in {0,1,2}), with
// u_i = x_i - CENTER_X:
//   sum_{i<j} (u_i+u_j)^2 = (n-2)*Sum(u^2) + (Sum u)^2
//   sum_{i<j} (y_i-y_j)^2 =  n   *Sum(y^2) - (Sum y)^2
//   #pairs                =  n(n-1)/2
// Both identities are exactly 0 for n in {0,1}.
//
// Two kernels, overlapped with Programmatic Dependent Launch: the finalize
// kernel launches concurrently with the per-batch kernel and blocks in
// cudaGridDependencySynchronize() (full memory visibility of kernel1's
// writes is guaranteed on return), hiding its launch latency.

#define CENTER_X 0.5f
#define BATCH 256
#define NPTS  512

__device__ float2 g_partial[BATCH];  // (loss, count) per batch

__global__ void __launch_bounds__(256) sym_per_batch(const float* __restrict__ kp,
                                                     const int* __restrict__ cls) {
    const int b = blockIdx.x;
    const int t = threadIdx.x;

    // Each thread handles 2 consecutive points: 1x float4 + 1x int2.
    const float4 p = reinterpret_cast<const float4*>(kp)[(size_t)b * 256 + t];
    const int2   c = reinterpret_cast<const int2*>(cls)[(size_t)b * 256 + t];

    float su[3], su2[3], sy[3], sy2[3], cn[3];
#pragma unroll
    for (int k = 0; k < 3; k++) { su[k] = su2[k] = sy[k] = sy2[k] = cn[k] = 0.0f; }

    const float ux[2] = {p.x - CENTER_X, p.z - CENTER_X};
    const float yy[2] = {p.y, p.w};
    const int   cc[2] = {c.x, c.y};
#pragma unroll
    for (int j = 0; j < 2; j++) {
#pragma unroll
        for (int k = 0; k < 3; k++) {
            if (cc[j] == k) {
                su[k]  += ux[j];
                su2[k]  = fmaf(ux[j], ux[j], su2[k]);
                sy[k]  += yy[j];
                sy2[k]  = fmaf(yy[j], yy[j], sy2[k]);
                cn[k]  += 1.0f;
            }
        }
    }

    // Intra-warp reduction (shuffles).
#pragma unroll
    for (int off = 16; off > 0; off >>= 1) {
#pragma unroll
        for (int k = 0; k < 3; k++) {
            su[k]  += __shfl_down_sync(0xffffffffu, su[k],  off);
            su2[k] += __shfl_down_sync(0xffffffffu, su2[k], off);
            sy[k]  += __shfl_down_sync(0xffffffffu, sy[k],  off);
            sy2[k] += __shfl_down_sync(0xffffffffu, sy2[k], off);
            cn[k]  += __shfl_down_sync(0xffffffffu, cn[k],  off);
        }
    }

    // Cross-warp via shared memory (8 warps).
    __shared__ float sf[8][15];
    const int wid = t >> 5, lid = t & 31;
    if (lid == 0) {
#pragma unroll
        for (int k = 0; k < 3; k++) {
            sf[wid][k * 5 + 0] = su[k];
            sf[wid][k * 5 + 1] = su2[k];
            sf[wid][k * 5 + 2] = sy[k];
            sf[wid][k * 5 + 3] = sy2[k];
            sf[wid][k * 5 + 4] = cn[k];
        }
    }
    __syncthreads();

    if (t == 0) {
        double loss = 0.0, count = 0.0;
#pragma unroll
        for (int k = 0; k < 3; k++) {
            double SU = 0.0, SU2 = 0.0, SY = 0.0, SY2 = 0.0, n = 0.0;
#pragma unroll
            for (int w = 0; w < 8; w++) {
                SU  += (double)sf[w][k * 5 + 0];
                SU2 += (double)sf[w][k * 5 + 1];
                SY  += (double)sf[w][k * 5 + 2];
                SY2 += (double)sf[w][k * 5 + 3];
                n   += (double)sf[w][k * 5 + 4];
            }
            loss  += (n - 2.0) * SU2 + SU * SU + n * SY2 - SY * SY;
            count += n * (n - 1.0) * 0.5;
        }
        g_partial[b] = make_float2((float)loss, (float)count);
    }

#if __CUDA_ARCH__ >= 900
    // Let the dependent finalize grid begin launching as soon as possible.
    cudaTriggerProgrammaticLaunchCompletion();
#endif
}

__global__ void __launch_bounds__(256) sym_finalize(float* __restrict__ out) {
#if __CUDA_ARCH__ >= 900
    // Wait for sym_per_batch to fully complete (makes g_partial visible).
    cudaGridDependencySynchronize();
#endif
    const int t = threadIdx.x;
    const float2 p = g_partial[t];
    double L = (double)p.x, C = (double)p.y;

#pragma unroll
    for (int off = 16; off > 0; off >>= 1) {
        L += __shfl_down_sync(0xffffffffu, L, off);
        C += __shfl_down_sync(0xffffffffu, C, off);
    }

    __shared__ double sl[8], sc[8];
    const int wid = t >> 5, lid = t & 31;
    if (lid == 0) { sl[wid] = L; sc[wid] = C; }
    __syncthreads();

    if (t == 0) {
        double TL = 0.0, TC = 0.0;
#pragma unroll
        for (int w = 0; w < 8; w++) { TL += sl[w]; TC += sc[w]; }
        const double c = TC < 1.0 ? 1.0 : TC;
        out[0] = (float)(TL / c);
    }
}

extern "C" void kernel_launch(void* const* d_in, const int* in_sizes, int n_in,
                              void* d_out, int out_size) {
    const float* kp  = (const float*)d_in[0];  // [256, 512, 2] f32
    const int*   cls = (const int*)d_in[1];    // [256, 512] i32
    float* out = (float*)d_out;

    sym_per_batch<<<BATCH, 256>>>(kp, cls);

    // Finalize with Programmatic Dependent Launch to overlap its launch
    // latency with sym_per_batch execution.
    cudaLaunchConfig_t cfg = {};
    cfg.gridDim  = dim3(1, 1, 1);
    cfg.blockDim = dim3(256, 1, 1);
    cfg.dynamicSmemBytes = 0;
    cfg.stream = 0;  // same (default) stream as the launch above
    cudaLaunchAttribute attr[1];
    attr[0].id = cudaLaunchAttributeProgrammaticStreamSerialization;
    attr[0].val.programmaticStreamSerializationAllowed = 1;
    cfg.attrs = attr;
    cfg.numAttrs = 1;

    cudaError_t e = cudaLaunchKernelEx(&cfg, sym_finalize, out);
    if (e != cudaSuccess) {
        // Fallback: plain serialized launch (R1 behavior).
        sym_finalize<<<1, 256>>>(out);
    }
}

// round 5
// speedup vs baseline: 2.9048x; 1.9762x over previous
#include <cuda_runtime.h>
#include <cuda_bf16.h>
#include <cstdint>

// Closed-form per-(batch,class) reduction of the symmetric-pair loss.
// For a group of n points of one symmetric class (c in {0,1,2}), with
// u_i = x_i - CENTER_X:
//   sum_{i<j} (u_i+u_j)^2 = (n-2)*Sum(u^2) + (Sum u)^2
//   sum_{i<j} (y_i-y_j)^2 =  n   *Sum(y^2) - (Sum y)^2
//   #pairs                =  n(n-1)/2
// Both identities are exactly 0 for n in {0,1}.
//
// kernel1: one CTA per batch, all-float math, warp-parallel cross-warp
//          reduce (no serial FP64 chain).
// finalize: PDL-overlapped, single warp, no smem/syncthreads; double only
//          for the final 256-element accumulation.

#define CENTER_X 0.5f
#define BATCH 256
#define NPTS  512

__device__ float2 g_partial[BATCH];  // (loss, count) per batch

__global__ void __launch_bounds__(256) sym_per_batch(const float* __restrict__ kp,
                                                     const int* __restrict__ cls) {
    const int b = blockIdx.x;
    const int t = threadIdx.x;

    // Each thread handles 2 consecutive points: 1x float4 + 1x int2.
    const float4 p = reinterpret_cast<const float4*>(kp)[(size_t)b * 256 + t];
    const int2   c = reinterpret_cast<const int2*>(cls)[(size_t)b * 256 + t];

    float acc[15];  // [class][su, su2, sy, sy2, cn]
#pragma unroll
    for (int k = 0; k < 15; k++) acc[k] = 0.0f;

    const float ux[2] = {p.x - CENTER_X, p.z - CENTER_X};
    const float yy[2] = {p.y, p.w};
    const int   cc[2] = {c.x, c.y};
#pragma unroll
    for (int j = 0; j < 2; j++) {
#pragma unroll
        for (int k = 0; k < 3; k++) {
            if (cc[j] == k) {
                acc[k * 5 + 0] += ux[j];
                acc[k * 5 + 1]  = fmaf(ux[j], ux[j], acc[k * 5 + 1]);
                acc[k * 5 + 2] += yy[j];
                acc[k * 5 + 3]  = fmaf(yy[j], yy[j], acc[k * 5 + 3]);
                acc[k * 5 + 4] += 1.0f;
            }
        }
    }

    // Intra-warp reduction (shuffles).
#pragma unroll
    for (int off = 16; off > 0; off >>= 1) {
#pragma unroll
        for (int k = 0; k < 15; k++)
            acc[k] += __shfl_down_sync(0xffffffffu, acc[k], off);
    }

    // Cross-warp: 8 warps publish 15 floats each.
    __shared__ float sf[8][16];  // padded row to dodge conflicts
    __shared__ float stot[16];
    const int wid = t >> 5, lid = t & 31;
    if (lid == 0) {
#pragma unroll
        for (int k = 0; k < 15; k++) sf[wid][k] = acc[k];
    }
    __syncthreads();

    // Warp 0, lanes 0..14: each lane sums one accumulator type across 8 warps.
    if (wid == 0) {
        if (lid < 15) {
            float s = 0.0f;
#pragma unroll
            for (int w = 0; w < 8; w++) s += sf[w][lid];
            stot[lid] = s;
        }
        __syncwarp();
        if (lid == 0) {
            float loss = 0.0f, count = 0.0f;
#pragma unroll
            for (int k = 0; k < 3; k++) {
                const float SU  = stot[k * 5 + 0];
                const float SU2 = stot[k * 5 + 1];
                const float SY  = stot[k * 5 + 2];
                const float SY2 = stot[k * 5 + 3];
                const float n   = stot[k * 5 + 4];
                loss  += (n - 2.0f) * SU2 + SU * SU + n * SY2 - SY * SY;
                count += n * (n - 1.0f) * 0.5f;
            }
            g_partial[b] = make_float2(loss, count);
        }
    }

#if __CUDA_ARCH__ >= 900
    cudaTriggerProgrammaticLaunchCompletion();
#endif
}

__global__ void __launch_bounds__(32) sym_finalize(float* __restrict__ out) {
#if __CUDA_ARCH__ >= 900
    cudaGridDependencySynchronize();  // full visibility of g_partial
#endif
    const int l = threadIdx.x;
    // 256 float2 partials = 128 float4; lane reads 4 coalesced float4 =
    // 8 (loss,count) pairs.
    const float4* p4 = reinterpret_cast<const float4*>(g_partial);
    double L = 0.0, C = 0.0;
#pragma unroll
    for (int i = 0; i < 4; i++) {
        const float4 v = p4[l + 32 * i];
        L += (double)v.x + (double)v.z;
        C += (double)v.y + (double)v.w;
    }
#pragma unroll
    for (int off = 16; off > 0; off >>= 1) {
        L += __shfl_down_sync(0xffffffffu, L, off);
        C += __shfl_down_sync(0xffffffffu, C, off);
    }
    if (l == 0) {
        const double c = C < 1.0 ? 1.0 : C;
        out[0] = (float)(L / c);
    }
}

extern "C" void kernel_launch(void* const* d_in, const int* in_sizes, int n_in,
                              void* d_out, int out_size) {
    const float* kp  = (const float*)d_in[0];  // [256, 512, 2] f32
    const int*   cls = (const int*)d_in[1];    // [256, 512] i32
    float* out = (float*)d_out;

    sym_per_batch<<<BATCH, 256>>>(kp, cls);

    // Finalize with Programmatic Dependent Launch to overlap launch latency.
    cudaLaunchConfig_t cfg = {};
    cfg.gridDim  = dim3(1, 1, 1);
    cfg.blockDim = dim3(32, 1, 1);
    cfg.dynamicSmemBytes = 0;
    cfg.stream = 0;
    cudaLaunchAttribute attr[1];
    attr[0].id = cudaLaunchAttributeProgrammaticStreamSerialization;
    attr[0].val.programmaticStreamSerializationAllowed = 1;
    cfg.attrs = attr;
    cfg.numAttrs = 1;

    cudaError_t e = cudaLaunchKernelEx(&cfg, sym_finalize, out);
    if (e != cudaSuccess) {
        sym_finalize<<<1, 32>>>(out);
    }
}